// round 5
// baseline (speedup 1.0000x reference)
#include <cuda_runtime.h>
#include <cuda_fp16.h>
#include <cstdint>

#define IN_F   4096
#define OUT_F  4096
#define MTOT   8192
#define RANK   16
#define QBLOCK 64
#define SCALING 2.0f

// Scratch (allocation-free rule: __device__ globals)
__device__ __half g_X[(size_t)MTOT * IN_F];    // 64 MB fp16 activations
__device__ __half g_W[(size_t)OUT_F * IN_F];   // 32 MB fp16 effective weight

// ---------------------------------------------------------------------------
// Kernel 0: no-op — keeps ncu's sampled launch (-s 5) on the GEMM.
// ---------------------------------------------------------------------------
__global__ void k_sample_shift() {}

// ---------------------------------------------------------------------------
// Kernel 1: convert x (fp32 -> fp16)  — 28us, HBM-bound, near-optimal.
// ---------------------------------------------------------------------------
__global__ void k_convert_x(const float* __restrict__ x) {
    size_t idx  = (size_t)blockIdx.x * blockDim.x + threadIdx.x;
    size_t base = idx * 8;
    const float4* xv = reinterpret_cast<const float4*>(x + base);
    float4 a = xv[0];
    float4 b = xv[1];
    __half2 h0 = __floats2half2_rn(a.x, a.y);
    __half2 h1 = __floats2half2_rn(a.z, a.w);
    __half2 h2 = __floats2half2_rn(b.x, b.y);
    __half2 h3 = __floats2half2_rn(b.z, b.w);
    uint4 o;
    o.x = *reinterpret_cast<unsigned*>(&h0);
    o.y = *reinterpret_cast<unsigned*>(&h1);
    o.z = *reinterpret_cast<unsigned*>(&h2);
    o.w = *reinterpret_cast<unsigned*>(&h3);
    reinterpret_cast<uint4*>(g_X)[idx] = o;
}

// ---------------------------------------------------------------------------
// Kernel 2: W_eff = dequant(q,scales) + SCALING * B@A  (fp16 out)
// ---------------------------------------------------------------------------
__global__ void k_build_w(const int*   __restrict__ q,
                          const float* __restrict__ sc,
                          const float* __restrict__ A,
                          const float* __restrict__ B) {
    __shared__ __align__(16) float Ash[RANK][512];   // 32 KB
    __shared__ __align__(16) float Bsh[128][16];     // 8 KB
    __shared__ float Ssh[128][8];                    // 4 KB scales

    const int t  = threadIdx.x;            // 256 threads
    const int i0 = blockIdx.x * 512;
    const int o0 = blockIdx.y * 128;

    #pragma unroll
    for (int j = 0; j < 8; j++) {
        int idx = t + 256 * j;
        int r   = idx >> 7;
        int c4  = idx & 127;
        float4 v = reinterpret_cast<const float4*>(A + (size_t)r * IN_F + i0)[c4];
        *reinterpret_cast<float4*>(&Ash[r][c4 * 4]) = v;
    }
    #pragma unroll
    for (int j = 0; j < 8; j++) {
        int idx = t + 256 * j;
        int o   = idx >> 4;
        int r   = idx & 15;
        Bsh[o][r] = B[(size_t)(o0 + o) * RANK + r] * SCALING;
    }
    if (t < 128) {
        #pragma unroll
        for (int blk = 0; blk < 8; blk++)
            Ssh[t][blk] = sc[(size_t)(o0 + t) * (IN_F / QBLOCK) + (i0 >> 6) + blk];
    }
    __syncthreads();

    const int lane = t & 31;
    const int wid  = t >> 5;

    #pragma unroll
    for (int j = 0; j < 4; j++) {
        const int il = (j * 32 + lane) * 4;
        float4 a[RANK];
        #pragma unroll
        for (int r = 0; r < RANK; r++)
            a[r] = *reinterpret_cast<const float4*>(&Ash[r][il]);

        #pragma unroll 2
        for (int oo = 0; oo < 16; oo++) {
            const int    ol   = (wid << 4) + oo;
            const int    o    = o0 + ol;
            const size_t orow = (size_t)o * IN_F;
            const int4   q4   = *reinterpret_cast<const int4*>(q + orow + i0 + il);
            const float  s    = Ssh[ol][il >> 6];

            float4 acc;
            acc.x = (float)(q4.x - 8) * s;
            acc.y = (float)(q4.y - 8) * s;
            acc.z = (float)(q4.z - 8) * s;
            acc.w = (float)(q4.w - 8) * s;

            const float4 b0 = *reinterpret_cast<const float4*>(&Bsh[ol][0]);
            const float4 b1 = *reinterpret_cast<const float4*>(&Bsh[ol][4]);
            const float4 b2 = *reinterpret_cast<const float4*>(&Bsh[ol][8]);
            const float4 b3 = *reinterpret_cast<const float4*>(&Bsh[ol][12]);
            const float bb[16] = { b0.x,b0.y,b0.z,b0.w, b1.x,b1.y,b1.z,b1.w,
                                   b2.x,b2.y,b2.z,b2.w, b3.x,b3.y,b3.z,b3.w };
            #pragma unroll
            for (int r = 0; r < RANK; r++) {
                acc.x += bb[r] * a[r].x;
                acc.y += bb[r] * a[r].y;
                acc.z += bb[r] * a[r].z;
                acc.w += bb[r] * a[r].w;
            }
            __half2 h0 = __floats2half2_rn(acc.x, acc.y);
            __half2 h1 = __floats2half2_rn(acc.z, acc.w);
            uint2 st;
            st.x = *reinterpret_cast<unsigned*>(&h0);
            st.y = *reinterpret_cast<unsigned*>(&h1);
            *reinterpret_cast<uint2*>(g_W + orow + i0 + il) = st;
        }
    }
}

// ---------------------------------------------------------------------------
// Kernel 3 (HMMA v3): out[M,N] = Xh @ W^T + bias
// CTA 128x256, 512 threads / 16 warps (4m x 4n), warp tile 32x64.
// 4-stage cp.async ring, SW128-swizzled smem, single __syncthreads per chunk,
// single-buffered fragments (regs ~110, no spills), occ 25%.
// ---------------------------------------------------------------------------
#define NSTAGE   4
#define STAGE_B  49152u                 // (128 A + 256 B) rows * 128B
#define SMEM_DYN (1024 + NSTAGE * STAGE_B)

__device__ __forceinline__ uint32_t smem_u32(const void* p) {
    uint32_t a;
    asm("{ .reg .u64 t; cvta.to.shared.u64 t, %1; cvt.u32.u64 %0, t; }"
        : "=r"(a) : "l"(p));
    return a;
}

__device__ __forceinline__ void cp16(uint32_t smem, const void* gmem) {
    asm volatile("cp.async.cg.shared.global [%0], [%1], 16;\n"
                 :: "r"(smem), "l"(gmem) : "memory");
}

__global__ void __launch_bounds__(512, 1) k_gemm(const float* __restrict__ bias,
                                                 float* __restrict__ out) {
    extern __shared__ char smem[];
    const uint32_t tiles = (smem_u32(smem) + 1023) & ~1023u;

    const int t    = threadIdx.x;         // 0..511
    const int lane = t & 31;
    const int wid  = t >> 5;              // 0..15
    const int wm   = wid & 3;             // 4 m-warps  (32 rows each)
    const int wn   = wid >> 2;            // 4 n-warps  (64 cols each)
    const int m0   = blockIdx.y * 128;
    const int n0   = blockIdx.x * 256;

    const __half* gA = g_X + (size_t)m0 * IN_F;
    const __half* gB = g_W + (size_t)n0 * IN_F;

    // cp.async geometry: 384 rows * 8 chunks = 3072 -> 6 per thread
    const int r0   = t >> 3;                                    // 0..63
    const int csrc = (t & 7) * 8;                               // K halves
    const uint32_t chs = (uint32_t)(((t & 7) ^ (r0 & 7)) << 4); // SW128 16B chunk

    auto fillf = [&](int f) {
        const uint32_t sb   = tiles + (uint32_t)(f & (NSTAGE - 1)) * STAGE_B;
        const int      koff = f * 64;
        #pragma unroll
        for (int j = 0; j < 2; j++) {                 // A: 128 rows
            int row = r0 + 64 * j;
            cp16(sb + (uint32_t)row * 128 + chs,
                 gA + (size_t)row * IN_F + koff + csrc);
        }
        #pragma unroll
        for (int j = 0; j < 4; j++) {                 // B: 256 rows
            int row = r0 + 64 * j;
            cp16(sb + 16384u + (uint32_t)row * 128 + chs,
                 gB + (size_t)row * IN_F + koff + csrc);
        }
    };

    float acc[2][8][4];
    #pragma unroll
    for (int i = 0; i < 2; i++)
        #pragma unroll
        for (int j = 0; j < 8; j++)
            #pragma unroll
            for (int k = 0; k < 4; k++) acc[i][j][k] = 0.f;

    // Prologue: 3 stages in flight, land stage 0
    fillf(0);
    asm volatile("cp.async.commit_group;\n" ::: "memory");
    fillf(1);
    asm volatile("cp.async.commit_group;\n" ::: "memory");
    fillf(2);
    asm volatile("cp.async.commit_group;\n" ::: "memory");
    asm volatile("cp.async.wait_group 2;\n" ::: "memory");
    __syncthreads();

    const int KT = IN_F / 64;   // 64 chunks
    for (int c = 0; c < KT; c++) {
        const uint32_t sa  = tiles + (uint32_t)(c & (NSTAGE - 1)) * STAGE_B;
        const uint32_t sbm = sa + 16384u;

        // issue next fill first: DMA overlaps tensor work below
        if (c + 3 < KT) fillf(c + 3);
        asm volatile("cp.async.commit_group;\n" ::: "memory");

        #pragma unroll
        for (int kc = 0; kc < 4; kc++) {
            uint32_t a[2][4];
            uint32_t b[8][2];
            #pragma unroll
            for (int mt = 0; mt < 2; mt++) {
                int row = wm * 32 + mt * 16 + (lane & 15);
                uint32_t addr = sa + (uint32_t)row * 128 +
                    ((uint32_t)(((kc * 2 + (lane >> 4)) ^ (row & 7))) << 4);
                asm volatile(
                    "ldmatrix.sync.aligned.m8n8.x4.shared.b16 {%0,%1,%2,%3}, [%4];\n"
                    : "=r"(a[mt][0]), "=r"(a[mt][1]), "=r"(a[mt][2]), "=r"(a[mt][3])
                    : "r"(addr));
            }
            #pragma unroll
            for (int g = 0; g < 4; g++) {
                int row = wn * 64 + g * 16 + (lane & 15);
                uint32_t addr = sbm + (uint32_t)row * 128 +
                    ((uint32_t)(((kc * 2 + (lane >> 4)) ^ (row & 7))) << 4);
                uint32_t q0, q1, q2, q3;
                asm volatile(
                    "ldmatrix.sync.aligned.m8n8.x4.shared.b16 {%0,%1,%2,%3}, [%4];\n"
                    : "=r"(q0), "=r"(q1), "=r"(q2), "=r"(q3)
                    : "r"(addr));
                b[g * 2 + 0][0] = q0; b[g * 2 + 0][1] = q2;
                b[g * 2 + 1][0] = q1; b[g * 2 + 1][1] = q3;
            }
            #pragma unroll
            for (int mt = 0; mt < 2; mt++) {
                #pragma unroll
                for (int nt = 0; nt < 8; nt++) {
                    asm volatile(
                        "mma.sync.aligned.m16n8k16.row.col.f32.f16.f16.f32 "
                        "{%0,%1,%2,%3}, {%4,%5,%6,%7}, {%8,%9}, {%0,%1,%2,%3};\n"
                        : "+f"(acc[mt][nt][0]), "+f"(acc[mt][nt][1]),
                          "+f"(acc[mt][nt][2]), "+f"(acc[mt][nt][3])
                        : "r"(a[mt][0]), "r"(a[mt][1]), "r"(a[mt][2]), "r"(a[mt][3]),
                          "r"(b[nt][0]), "r"(b[nt][1]));
                }
            }
        }

        asm volatile("cp.async.wait_group 2;\n" ::: "memory");
        __syncthreads();
    }

    // Epilogue: += bias
    #pragma unroll
    for (int mt = 0; mt < 2; mt++) {
        int row = m0 + wm * 32 + mt * 16 + (lane >> 2);
        #pragma unroll
        for (int nt = 0; nt < 8; nt++) {
            int col = n0 + wn * 64 + nt * 8 + (lane & 3) * 2;
            float b0 = bias[col];
            float b1 = bias[col + 1];
            float2 v0 = make_float2(acc[mt][nt][0] + b0, acc[mt][nt][1] + b1);
            float2 v1 = make_float2(acc[mt][nt][2] + b0, acc[mt][nt][3] + b1);
            *reinterpret_cast<float2*>(out + (size_t)row * OUT_F + col)       = v0;
            *reinterpret_cast<float2*>(out + (size_t)(row + 8) * OUT_F + col) = v1;
        }
    }
}

// ---------------------------------------------------------------------------
extern "C" void kernel_launch(void* const* d_in, const int* in_sizes, int n_in,
                              void* d_out, int out_size) {
    const float* x    = (const float*)d_in[0];
    const int*   q    = (const int*)  d_in[1];
    const float* sc   = (const float*)d_in[2];
    const float* bias = (const float*)d_in[3];
    const float* A    = (const float*)d_in[4];
    const float* B    = (const float*)d_in[5];
    float*       out  = (float*)d_out;

    (void)in_sizes; (void)n_in; (void)out_size;

    cudaFuncSetAttribute(k_gemm, cudaFuncAttributeMaxDynamicSharedMemorySize,
                         SMEM_DYN);

    k_sample_shift<<<1, 32>>>();
    k_convert_x<<<(MTOT * (size_t)IN_F) / (256 * 8), 256>>>(x);
    k_build_w<<<dim3(IN_F / 512, OUT_F / 128), 256>>>(q, sc, A, B);
    k_gemm<<<dim3(OUT_F / 256, MTOT / 128), 512, SMEM_DYN>>>(bias, out);
}